// round 1
// baseline (speedup 1.0000x reference)
#include <cuda_runtime.h>

#define NPC   110592            // 48*48*48 elements per channel
#define NCH   128
#define NTOT  (NPC * NCH)       // 14155776

// Per-channel transformed parameters (written by prep_kernel):
// [0]=affine flag, [1]=G, [2]=H,
// [3..5]=softplus(m0), [6..8]=b0, [9..11]=tanh(f0),
// [12..20]=softplus(m1), [21..23]=b1, [24..26]=tanh(f1),
// [27..35]=softplus(m2), [36..38]=b2, [39..41]=tanh(f2),
// [42..44]=softplus(m3), [45]=b3
__device__ float g_params[NCH][48];

__device__ __forceinline__ float softplus_acc(float v) {
    return v > 20.0f ? v : log1pf(expf(v));
}

__device__ __forceinline__ float fast_tanh(float x) {
    float r;
    asm("tanh.approx.f32 %0, %1;" : "=f"(r) : "f"(x));
    return r;
}

__device__ __forceinline__ float sigmoidf_fast(float t) {
    return __fdividef(1.0f, 1.0f + __expf(-t));
}

// ---------------------------------------------------------------------------
// Prep: transform raw params, test affine degeneracy, compose G/H per channel
// ---------------------------------------------------------------------------
__global__ void prep_kernel(const float* __restrict__ m0, const float* __restrict__ m1,
                            const float* __restrict__ m2, const float* __restrict__ m3,
                            const float* __restrict__ b0, const float* __restrict__ b1,
                            const float* __restrict__ b2, const float* __restrict__ b3,
                            const float* __restrict__ f0, const float* __restrict__ f1,
                            const float* __restrict__ f2) {
    int c = threadIdx.x;
    if (c >= NCH) return;
    float* P = g_params[c];

    float a0[3], B0v[3], T0[3], W1[9], B1v[3], T1[3], W2[9], B2v[3], T2[3], w3[3], B3v;
    #pragma unroll
    for (int j = 0; j < 3; j++) {
        a0[j]  = softplus_acc(m0[c * 3 + j]);
        B0v[j] = b0[c * 3 + j];
        T0[j]  = tanhf(f0[c * 3 + j]);
        B1v[j] = b1[c * 3 + j];
        T1[j]  = tanhf(f1[c * 3 + j]);
        B2v[j] = b2[c * 3 + j];
        T2[j]  = tanhf(f2[c * 3 + j]);
        w3[j]  = softplus_acc(m3[c * 3 + j]);
    }
    #pragma unroll
    for (int j = 0; j < 9; j++) {
        W1[j] = softplus_acc(m1[c * 9 + j]);
        W2[j] = softplus_acc(m2[c * 9 + j]);
    }
    B3v = b3[c];

    bool affine = true;
    #pragma unroll
    for (int j = 0; j < 3; j++)
        affine = affine && (T0[j] == 0.0f) && (T1[j] == 0.0f) && (T2[j] == 0.0f);

    // Compose affine chain: logit(z) = G*z + H (valid when all tanh-factors are 0)
    float g1[3], o1[3], g2[3], o2[3];
    #pragma unroll
    for (int j = 0; j < 3; j++) {
        g1[j] = W1[j*3+0]*a0[0]  + W1[j*3+1]*a0[1]  + W1[j*3+2]*a0[2];
        o1[j] = W1[j*3+0]*B0v[0] + W1[j*3+1]*B0v[1] + W1[j*3+2]*B0v[2] + B1v[j];
    }
    #pragma unroll
    for (int j = 0; j < 3; j++) {
        g2[j] = W2[j*3+0]*g1[0] + W2[j*3+1]*g1[1] + W2[j*3+2]*g1[2];
        o2[j] = W2[j*3+0]*o1[0] + W2[j*3+1]*o1[1] + W2[j*3+2]*o1[2] + B2v[j];
    }
    float G = w3[0]*g2[0] + w3[1]*g2[1] + w3[2]*g2[2];
    float H = w3[0]*o2[0] + w3[1]*o2[1] + w3[2]*o2[2] + B3v;

    P[0] = affine ? 1.0f : 0.0f;
    P[1] = G;
    P[2] = H;
    #pragma unroll
    for (int j = 0; j < 3; j++) {
        P[3 + j]  = a0[j];  P[6 + j]  = B0v[j]; P[9 + j]  = T0[j];
        P[21 + j] = B1v[j]; P[24 + j] = T1[j];
        P[36 + j] = B2v[j]; P[39 + j] = T2[j];
        P[42 + j] = w3[j];
    }
    #pragma unroll
    for (int j = 0; j < 9; j++) { P[12 + j] = W1[j]; P[27 + j] = W2[j]; }
    P[45] = B3v;
}

// Full 4-layer MLP (fallback path, only taken if some tanh-factor != 0)
__device__ __forceinline__ float mlp_full(float z, const float* p) {
    float h0 = fmaf(p[3], z, p[6]);  h0 = fmaf(p[9],  fast_tanh(h0), h0);
    float h1 = fmaf(p[4], z, p[7]);  h1 = fmaf(p[10], fast_tanh(h1), h1);
    float h2 = fmaf(p[5], z, p[8]);  h2 = fmaf(p[11], fast_tanh(h2), h2);

    float g0 = fmaf(p[12], h0, fmaf(p[13], h1, fmaf(p[14], h2, p[21])));
    float g1 = fmaf(p[15], h0, fmaf(p[16], h1, fmaf(p[17], h2, p[22])));
    float g2 = fmaf(p[18], h0, fmaf(p[19], h1, fmaf(p[20], h2, p[23])));
    g0 = fmaf(p[24], fast_tanh(g0), g0);
    g1 = fmaf(p[25], fast_tanh(g1), g1);
    g2 = fmaf(p[26], fast_tanh(g2), g2);

    float k0 = fmaf(p[27], g0, fmaf(p[28], g1, fmaf(p[29], g2, p[36])));
    float k1 = fmaf(p[30], g0, fmaf(p[31], g1, fmaf(p[32], g2, p[37])));
    float k2 = fmaf(p[33], g0, fmaf(p[34], g1, fmaf(p[35], g2, p[38])));
    k0 = fmaf(p[39], fast_tanh(k0), k0);
    k1 = fmaf(p[40], fast_tanh(k1), k1);
    k2 = fmaf(p[41], fast_tanh(k2), k2);

    return fmaf(p[42], k0, fmaf(p[43], k1, fmaf(p[44], k2, p[45])));
}

__device__ __forceinline__ float lik_from_logits(float l, float u) {
    float s = l + u;
    if (s == 0.0f) return 1e-9f;   // replicate sign(0)=0 -> likelihood 0 -> bound
    float v = fabsf(sigmoidf_fast(u) - sigmoidf_fast(l));
    return fmaxf(v, 1e-9f);
}

// ---------------------------------------------------------------------------
// Main streaming kernel: 4 elements/thread via float4, one channel per blockIdx.y
// ---------------------------------------------------------------------------
__global__ void __launch_bounds__(256)
main_kernel(const float* __restrict__ x, const float* __restrict__ noise,
            float* __restrict__ outp, float* __restrict__ lik) {
    __shared__ float sp[48];
    int c = blockIdx.y;
    if (threadIdx.x < 48) sp[threadIdx.x] = g_params[c][threadIdx.x];
    __syncthreads();

    int base = c * NPC + blockIdx.x * 1024 + threadIdx.x * 4;

    float4 xv = *(const float4*)(x + base);
    float4 nv = *(const float4*)(noise + base);

    // outputs = x + (noise - 0.5)   (exact rounding order as reference)
    float z0 = xv.x + (nv.x - 0.5f);
    float z1 = xv.y + (nv.y - 0.5f);
    float z2 = xv.z + (nv.z - 0.5f);
    float z3 = xv.w + (nv.w - 0.5f);
    *(float4*)(outp + base) = make_float4(z0, z1, z2, z3);

    float4 L;
    if (sp[0] != 0.0f) {
        float G  = sp[1];
        float Hl = sp[2] - 0.5f * G;
        float Hu = sp[2] + 0.5f * G;
        L.x = lik_from_logits(fmaf(G, z0, Hl), fmaf(G, z0, Hu));
        L.y = lik_from_logits(fmaf(G, z1, Hl), fmaf(G, z1, Hu));
        L.z = lik_from_logits(fmaf(G, z2, Hl), fmaf(G, z2, Hu));
        L.w = lik_from_logits(fmaf(G, z3, Hl), fmaf(G, z3, Hu));
    } else {
        L.x = lik_from_logits(mlp_full(z0 - 0.5f, sp), mlp_full(z0 + 0.5f, sp));
        L.y = lik_from_logits(mlp_full(z1 - 0.5f, sp), mlp_full(z1 + 0.5f, sp));
        L.z = lik_from_logits(mlp_full(z2 - 0.5f, sp), mlp_full(z2 + 0.5f, sp));
        L.w = lik_from_logits(mlp_full(z3 - 0.5f, sp), mlp_full(z3 + 0.5f, sp));
    }
    *(float4*)(lik + base) = L;
}

// ---------------------------------------------------------------------------
// Quantiles loss: 128 threads, one per channel, accurate sequential MLP
// ---------------------------------------------------------------------------
__global__ void quant_kernel(const float* __restrict__ q, float* __restrict__ out_scalar) {
    __shared__ float red[128];
    int c = threadIdx.x;

    const float T = (float)log(2.0 / 1e-9 - 1.0);
    float tgt[3] = { -T, 0.0f, T };
    const float* p = g_params[c];

    float loss = 0.0f;
    #pragma unroll
    for (int i = 0; i < 3; i++) {
        float z = q[c * 3 + i];
        float h0 = fmaf(p[3], z, p[6]);  h0 = fmaf(p[9],  tanhf(h0), h0);
        float h1 = fmaf(p[4], z, p[7]);  h1 = fmaf(p[10], tanhf(h1), h1);
        float h2 = fmaf(p[5], z, p[8]);  h2 = fmaf(p[11], tanhf(h2), h2);

        float g0 = p[12]*h0 + p[13]*h1 + p[14]*h2 + p[21];
        float g1 = p[15]*h0 + p[16]*h1 + p[17]*h2 + p[22];
        float g2 = p[18]*h0 + p[19]*h1 + p[20]*h2 + p[23];
        g0 += p[24] * tanhf(g0);
        g1 += p[25] * tanhf(g1);
        g2 += p[26] * tanhf(g2);

        float k0 = p[27]*g0 + p[28]*g1 + p[29]*g2 + p[36];
        float k1 = p[30]*g0 + p[31]*g1 + p[32]*g2 + p[37];
        float k2 = p[33]*g0 + p[34]*g1 + p[35]*g2 + p[38];
        k0 += p[39] * tanhf(k0);
        k1 += p[40] * tanhf(k1);
        k2 += p[41] * tanhf(k2);

        float o = p[42]*k0 + p[43]*k1 + p[44]*k2 + p[45];
        loss += fabsf(o - tgt[i]);
    }

    red[c] = loss;
    __syncthreads();
    #pragma unroll
    for (int s = 64; s > 0; s >>= 1) {
        if (c < s) red[c] += red[c + s];
        __syncthreads();
    }
    if (c == 0) *out_scalar = red[0];
}

// ---------------------------------------------------------------------------
// Launch
// ---------------------------------------------------------------------------
extern "C" void kernel_launch(void* const* d_in, const int* in_sizes, int n_in,
                              void* d_out, int out_size) {
    const float* x     = (const float*)d_in[0];
    const float* noise = (const float*)d_in[1];
    const float *m0, *m1, *m2, *m3, *b0, *b1, *b2, *b3, *f0, *f1, *f2, *q;

    // Disambiguate input ordering from element counts:
    //   signature order: x,noise,m0,m1,m2,m3,b0..b3,f0..f2,quantiles -> in_sizes[3]==1152
    //   dict order:      x,noise,m0,b0,f0,m1,b1,f1,m2,b2,f2,m3,b3,q  -> in_sizes[5]==1152
    if (n_in >= 14 && in_sizes[3] == 1152) {
        m0 = (const float*)d_in[2];  m1 = (const float*)d_in[3];
        m2 = (const float*)d_in[4];  m3 = (const float*)d_in[5];
        b0 = (const float*)d_in[6];  b1 = (const float*)d_in[7];
        b2 = (const float*)d_in[8];  b3 = (const float*)d_in[9];
        f0 = (const float*)d_in[10]; f1 = (const float*)d_in[11];
        f2 = (const float*)d_in[12]; q  = (const float*)d_in[13];
    } else {
        m0 = (const float*)d_in[2];  b0 = (const float*)d_in[3];
        f0 = (const float*)d_in[4];  m1 = (const float*)d_in[5];
        b1 = (const float*)d_in[6];  f1 = (const float*)d_in[7];
        m2 = (const float*)d_in[8];  b2 = (const float*)d_in[9];
        f2 = (const float*)d_in[10]; m3 = (const float*)d_in[11];
        b3 = (const float*)d_in[12]; q  = (const float*)d_in[13];
    }

    float* out   = (float*)d_out;
    float* lik   = out + NTOT;
    float* qloss = out + 2 * (long long)NTOT;

    prep_kernel<<<1, 128>>>(m0, m1, m2, m3, b0, b1, b2, b3, f0, f1, f2);

    dim3 grid(NPC / 1024, NCH);
    main_kernel<<<grid, 256>>>(x, noise, out, lik);

    quant_kernel<<<1, 128>>>(q, qloss);
}